// round 1
// baseline (speedup 1.0000x reference)
#include <cuda_runtime.h>

#define BN_EPS 1e-5f

// ---------------- scratch (device globals; no allocations allowed) ----------------
__device__ float g_w1f[32 * 27];          // folded conv1 weights [c][k]
__device__ float g_b1f[32];
__device__ float g_w2t[27 * 32 * 64];     // folded conv2 weights [(kk*32+ci)*64 + co]
__device__ float g_b2f[64];
__device__ float g_w3t[27 * 64 * 128];    // folded conv3 weights [(kk*64+ci)*128 + co]
__device__ float g_b3f[128];
__device__ float g_a1[16 * 343 * 32];     // conv1 cone activations [b][pos(7^3)][ci]
__device__ float g_a2[16 * 27 * 64];      // conv2 cone activations [b][pos(3^3)][co]

// ---------------- K0: fold BN into weights, transpose for coalesced reads ----------
__global__ void prep_kernel(
    const float* __restrict__ w1, const float* __restrict__ g1, const float* __restrict__ b1,
    const float* __restrict__ m1, const float* __restrict__ v1,
    const float* __restrict__ w2, const float* __restrict__ g2, const float* __restrict__ b2,
    const float* __restrict__ m2, const float* __restrict__ v2,
    const float* __restrict__ w3, const float* __restrict__ g3, const float* __restrict__ b3,
    const float* __restrict__ m3, const float* __restrict__ v3)
{
    int i = blockIdx.x * blockDim.x + threadIdx.x;
    int nth = gridDim.x * blockDim.x;

    if (i < 32) {
        float s = g1[i] * rsqrtf(v1[i] + BN_EPS);
        g_b1f[i] = b1[i] - m1[i] * s;
    } else if (i < 96) {
        int c = i - 32;
        float s = g2[c] * rsqrtf(v2[c] + BN_EPS);
        g_b2f[c] = b2[c] - m2[c] * s;
    } else if (i < 224) {
        int c = i - 96;
        float s = g3[c] * rsqrtf(v3[c] + BN_EPS);
        g_b3f[c] = b3[c] - m3[c] * s;
    }

    // w1f[c*27+k] = w1[c][0][k] * s1[c]
    for (int j = i; j < 32 * 27; j += nth) {
        int c = j / 27;
        float s = g1[c] * rsqrtf(v1[c] + BN_EPS);
        g_w1f[j] = w1[j] * s;
    }
    // w2t[(kk*32+ci)*64+co] = w2[co][ci][kk] * s2[co]
    for (int j = i; j < 27 * 32 * 64; j += nth) {
        int co = j & 63;
        int r  = j >> 6;
        int ci = r & 31;
        int kk = r >> 5;
        float s = g2[co] * rsqrtf(v2[co] + BN_EPS);
        g_w2t[j] = w2[(co * 32 + ci) * 27 + kk] * s;
    }
    // w3t[(kk*64+ci)*128+co] = w3[co][ci][kk] * s3[co]
    for (int j = i; j < 27 * 64 * 128; j += nth) {
        int co = j & 127;
        int r  = j >> 7;
        int ci = r & 63;
        int kk = r >> 6;
        float s = g3[co] * rsqrtf(v3[co] + BN_EPS);
        g_w3t[j] = w3[(co * 64 + ci) * 27 + kk] * s;
    }
}

// ---------------- K1: conv1+BN+ReLU on the 7^3 cone ---------------------------------
// grid = 16 batches * 7 z-slices. Output z' = 29+zi needs input z in [28+zi, 30+zi].
__global__ void conv1_kernel(const float* __restrict__ voxel)
{
    __shared__ float s_in[3 * 9 * 9];
    __shared__ float s_w[32 * 27];
    __shared__ float s_b[32];

    int b  = blockIdx.x / 7;
    int zi = blockIdx.x % 7;
    int tid = threadIdx.x;

    for (int i = tid; i < 3 * 9 * 9; i += 256) {
        int lz = i / 81, r = i % 81, ly = r / 9, lx = r % 9;
        s_in[i] = voxel[(size_t)b * 262144 + (size_t)(28 + zi + lz) * 4096
                        + (28 + ly) * 64 + (28 + lx)];
    }
    for (int i = tid; i < 864; i += 256) s_w[i] = g_w1f[i];
    if (tid < 32) s_b[tid] = g_b1f[tid];
    __syncthreads();

    if (tid < 196) {
        int pos = tid % 49;   // yi*7 + xi
        int cg  = tid / 49;   // channel group of 8
        int yi = pos / 7, xi = pos % 7;

        float x[27];
#pragma unroll
        for (int kz = 0; kz < 3; kz++)
#pragma unroll
            for (int ky = 0; ky < 3; ky++)
#pragma unroll
                for (int kx = 0; kx < 3; kx++)
                    x[kz * 9 + ky * 3 + kx] = s_in[kz * 81 + (yi + ky) * 9 + (xi + kx)];

        int p3 = zi * 49 + pos;
#pragma unroll
        for (int cc = 0; cc < 8; cc++) {
            int c = cg * 8 + cc;
            float acc = s_b[c];
#pragma unroll
            for (int k = 0; k < 27; k++)
                acc = fmaf(x[k], s_w[c * 27 + k], acc);
            g_a1[((size_t)b * 343 + p3) * 32 + c] = fmaxf(acc, 0.f);
        }
    }
}

// ---------------- K2: conv2+BN+ReLU on the 3^3 cone ---------------------------------
// grid = 16 batches * 27 output positions. Each block: 64 channels at one position.
__global__ void conv2_kernel()
{
    __shared__ float s_patch[864];   // [kk*32 + ci]
    __shared__ float s_red[256];

    int blk = blockIdx.x;
    int b = blk / 27, p = blk % 27;
    int pz = p / 9, py = (p / 3) % 3, px = p % 3;
    int tid = threadIdx.x;

    for (int i = tid; i < 864; i += 256) {
        int ci = i & 31, kk = i >> 5;
        int kz = kk / 9, ky = (kk / 3) % 3, kx = kk % 3;
        int apos = (2 * pz + kz) * 49 + (2 * py + ky) * 7 + (2 * px + kx);
        s_patch[i] = g_a1[((size_t)b * 343 + apos) * 32 + ci];
    }
    __syncthreads();

    int co = tid & 63;
    int ks = tid >> 6;          // 4-way K split, 216 each
    int k0 = ks * 216;
    float a0 = 0.f, a1 = 0.f, a2 = 0.f, a3 = 0.f;
#pragma unroll 4
    for (int k = k0; k < k0 + 216; k += 4) {
        a0 = fmaf(s_patch[k + 0], g_w2t[(k + 0) * 64 + co], a0);
        a1 = fmaf(s_patch[k + 1], g_w2t[(k + 1) * 64 + co], a1);
        a2 = fmaf(s_patch[k + 2], g_w2t[(k + 2) * 64 + co], a2);
        a3 = fmaf(s_patch[k + 3], g_w2t[(k + 3) * 64 + co], a3);
    }
    s_red[tid] = (a0 + a1) + (a2 + a3);
    __syncthreads();

    if (tid < 64) {
        float v = s_red[tid] + s_red[tid + 64] + s_red[tid + 128] + s_red[tid + 192]
                + g_b2f[tid];
        g_a2[((size_t)b * 27 + p) * 64 + tid] = fmaxf(v, 0.f);
    }
}

// ---------------- K3: conv3+BN+ReLU at center, then 128x256 projection ---------------
__global__ void conv3_proj_kernel(const float* __restrict__ wp,
                                  const float* __restrict__ bp,
                                  float* __restrict__ out)
{
    __shared__ float s_patch[1728];   // [kk*64 + ci]  == g_a2[b] verbatim
    __shared__ float s_red[256];
    __shared__ float s_center[128];

    int b = blockIdx.x;
    int tid = threadIdx.x;

    for (int i = tid; i < 1728; i += 256)
        s_patch[i] = g_a2[(size_t)b * 1728 + i];
    __syncthreads();

    int co = tid & 127;
    int ks = tid >> 7;          // 2-way K split, 864 each
    int k0 = ks * 864;
    float a0 = 0.f, a1 = 0.f, a2 = 0.f, a3 = 0.f;
#pragma unroll 4
    for (int k = k0; k < k0 + 864; k += 4) {
        a0 = fmaf(s_patch[k + 0], g_w3t[(k + 0) * 128 + co], a0);
        a1 = fmaf(s_patch[k + 1], g_w3t[(k + 1) * 128 + co], a1);
        a2 = fmaf(s_patch[k + 2], g_w3t[(k + 2) * 128 + co], a2);
        a3 = fmaf(s_patch[k + 3], g_w3t[(k + 3) * 128 + co], a3);
    }
    s_red[tid] = (a0 + a1) + (a2 + a3);
    __syncthreads();

    if (tid < 128) {
        float v = s_red[tid] + s_red[tid + 128] + g_b3f[tid];
        s_center[tid] = fmaxf(v, 0.f);
    }
    __syncthreads();

    // projection: out[b][f] = bp[f] + sum_c center[c] * wp[c*256+f]
    float o = bp[tid];
#pragma unroll 4
    for (int c = 0; c < 128; c++)
        o = fmaf(s_center[c], wp[c * 256 + tid], o);
    out[b * 256 + tid] = o;
}

// ---------------- launch -------------------------------------------------------------
extern "C" void kernel_launch(void* const* d_in, const int* in_sizes, int n_in,
                              void* d_out, int out_size)
{
    const float* voxel = (const float*)d_in[0];
    const float* w1 = (const float*)d_in[1];
    const float* g1 = (const float*)d_in[2];
    const float* b1 = (const float*)d_in[3];
    const float* m1 = (const float*)d_in[4];
    const float* v1 = (const float*)d_in[5];
    const float* w2 = (const float*)d_in[6];
    const float* g2 = (const float*)d_in[7];
    const float* b2 = (const float*)d_in[8];
    const float* m2 = (const float*)d_in[9];
    const float* v2 = (const float*)d_in[10];
    const float* w3 = (const float*)d_in[11];
    const float* g3 = (const float*)d_in[12];
    const float* b3 = (const float*)d_in[13];
    const float* m3 = (const float*)d_in[14];
    const float* v3 = (const float*)d_in[15];
    const float* wp = (const float*)d_in[16];
    const float* bp = (const float*)d_in[17];

    prep_kernel<<<432, 256>>>(w1, g1, b1, m1, v1,
                              w2, g2, b2, m2, v2,
                              w3, g3, b3, m3, v3);
    conv1_kernel<<<112, 256>>>(voxel);
    conv2_kernel<<<432, 256>>>();
    conv3_proj_kernel<<<16, 256>>>(wp, bp, (float*)d_out);
}

// round 3
// speedup vs baseline: 2.1420x; 2.1420x over previous
#include <cuda_runtime.h>

#define BN_EPS 1e-5f

// ---------------- scratch (device globals; no allocations allowed) ----------------
__device__ float g_w1f[32 * 27];          // folded conv1 weights [c][k]
__device__ float g_b1f[32];
__device__ float g_w2t[27 * 32 * 64];     // folded conv2 weights [(kk*32+ci)*64 + co]
__device__ float g_b2f[64];
__device__ float g_w3t[27 * 64 * 128];    // folded conv3 weights [(kk*64+ci)*128 + co]
__device__ float g_b3f[128];
__device__ float g_a1[16 * 343 * 32];     // conv1 cone activations [b][pos(7^3)][ci]
__device__ float g_a2[16 * 27 * 64];      // conv2 cone activations [b][pos(3^3)][co]
__device__ float g_p3[8 * 16 * 128];      // conv3 K-split partials [kc][b][co]

// ---------------- K0: fold BN into weights, transpose for coalesced reads ----------
__global__ void prep_kernel(
    const float* __restrict__ w1, const float* __restrict__ g1, const float* __restrict__ b1,
    const float* __restrict__ m1, const float* __restrict__ v1,
    const float* __restrict__ w2, const float* __restrict__ g2, const float* __restrict__ b2,
    const float* __restrict__ m2, const float* __restrict__ v2,
    const float* __restrict__ w3, const float* __restrict__ g3, const float* __restrict__ b3,
    const float* __restrict__ m3, const float* __restrict__ v3)
{
    int i = blockIdx.x * blockDim.x + threadIdx.x;
    int nth = gridDim.x * blockDim.x;

    if (i < 32) {
        float s = g1[i] * rsqrtf(v1[i] + BN_EPS);
        g_b1f[i] = b1[i] - m1[i] * s;
    } else if (i < 96) {
        int c = i - 32;
        float s = g2[c] * rsqrtf(v2[c] + BN_EPS);
        g_b2f[c] = b2[c] - m2[c] * s;
    } else if (i < 224) {
        int c = i - 96;
        float s = g3[c] * rsqrtf(v3[c] + BN_EPS);
        g_b3f[c] = b3[c] - m3[c] * s;
    }

    // w1f[c*27+k] = w1[c][0][k] * s1[c]
    for (int j = i; j < 32 * 27; j += nth) {
        int c = j / 27;
        float s = g1[c] * rsqrtf(v1[c] + BN_EPS);
        g_w1f[j] = w1[j] * s;
    }
    // w2t[(kk*32+ci)*64+co] = w2[co][ci][kk] * s2[co]
    for (int j = i; j < 27 * 32 * 64; j += nth) {
        int co = j & 63;
        int r  = j >> 6;
        int ci = r & 31;
        int kk = r >> 5;
        float s = g2[co] * rsqrtf(v2[co] + BN_EPS);
        g_w2t[j] = w2[(co * 32 + ci) * 27 + kk] * s;
    }
    // w3t[(kk*64+ci)*128+co] = w3[co][ci][kk] * s3[co]
    for (int j = i; j < 27 * 64 * 128; j += nth) {
        int co = j & 127;
        int r  = j >> 7;
        int ci = r & 63;
        int kk = r >> 6;
        float s = g3[co] * rsqrtf(v3[co] + BN_EPS);
        g_w3t[j] = w3[(co * 64 + ci) * 27 + kk] * s;
    }
}

// ---------------- K1: conv1+BN+ReLU on the 7^3 cone ---------------------------------
// grid = 16 batches * 7 z-slices. Output z' = 29+zi needs input z in [28+zi, 30+zi].
__global__ void conv1_kernel(const float* __restrict__ voxel)
{
    __shared__ float s_in[3 * 9 * 9];
    __shared__ float s_w[32 * 27];
    __shared__ float s_b[32];

    int b  = blockIdx.x / 7;
    int zi = blockIdx.x % 7;
    int tid = threadIdx.x;

    for (int i = tid; i < 3 * 9 * 9; i += 256) {
        int lz = i / 81, r = i % 81, ly = r / 9, lx = r % 9;
        s_in[i] = voxel[(size_t)b * 262144 + (size_t)(28 + zi + lz) * 4096
                        + (28 + ly) * 64 + (28 + lx)];
    }
    for (int i = tid; i < 864; i += 256) s_w[i] = g_w1f[i];
    if (tid < 32) s_b[tid] = g_b1f[tid];
    __syncthreads();

    if (tid < 196) {
        int pos = tid % 49;   // yi*7 + xi
        int cg  = tid / 49;   // channel group of 8
        int yi = pos / 7, xi = pos % 7;

        float x[27];
#pragma unroll
        for (int kz = 0; kz < 3; kz++)
#pragma unroll
            for (int ky = 0; ky < 3; ky++)
#pragma unroll
                for (int kx = 0; kx < 3; kx++)
                    x[kz * 9 + ky * 3 + kx] = s_in[kz * 81 + (yi + ky) * 9 + (xi + kx)];

        int p3 = zi * 49 + pos;
#pragma unroll
        for (int cc = 0; cc < 8; cc++) {
            int c = cg * 8 + cc;
            float acc = s_b[c];
#pragma unroll
            for (int k = 0; k < 27; k++)
                acc = fmaf(x[k], s_w[c * 27 + k], acc);
            g_a1[((size_t)b * 343 + p3) * 32 + c] = fmaxf(acc, 0.f);
        }
    }
}

// ---------------- K2: conv2+BN+ReLU on the 3^3 cone ---------------------------------
// grid = 16 batches * 27 output positions. Each block: 64 channels at one position.
__global__ void conv2_kernel()
{
    __shared__ float s_patch[864];   // [kk*32 + ci]
    __shared__ float s_red[256];

    int blk = blockIdx.x;
    int b = blk / 27, p = blk % 27;
    int pz = p / 9, py = (p / 3) % 3, px = p % 3;
    int tid = threadIdx.x;

    for (int i = tid; i < 864; i += 256) {
        int ci = i & 31, kk = i >> 5;
        int kz = kk / 9, ky = (kk / 3) % 3, kx = kk % 3;
        int apos = (2 * pz + kz) * 49 + (2 * py + ky) * 7 + (2 * px + kx);
        s_patch[i] = g_a1[((size_t)b * 343 + apos) * 32 + ci];
    }
    __syncthreads();

    int co = tid & 63;
    int ks = tid >> 6;          // 4-way K split, 216 each
    int k0 = ks * 216;
    const float* wp2 = g_w2t + co;
    // 8 independent accumulators -> MLP ~8 on the weight loads
    float a0 = 0.f, a1 = 0.f, a2 = 0.f, a3 = 0.f;
    float a4 = 0.f, a5 = 0.f, a6 = 0.f, a7 = 0.f;
    for (int k = k0; k < k0 + 216; k += 8) {
        a0 = fmaf(s_patch[k + 0], wp2[(k + 0) * 64], a0);
        a1 = fmaf(s_patch[k + 1], wp2[(k + 1) * 64], a1);
        a2 = fmaf(s_patch[k + 2], wp2[(k + 2) * 64], a2);
        a3 = fmaf(s_patch[k + 3], wp2[(k + 3) * 64], a3);
        a4 = fmaf(s_patch[k + 4], wp2[(k + 4) * 64], a4);
        a5 = fmaf(s_patch[k + 5], wp2[(k + 5) * 64], a5);
        a6 = fmaf(s_patch[k + 6], wp2[(k + 6) * 64], a6);
        a7 = fmaf(s_patch[k + 7], wp2[(k + 7) * 64], a7);
    }
    s_red[tid] = ((a0 + a1) + (a2 + a3)) + ((a4 + a5) + (a6 + a7));
    __syncthreads();

    if (tid < 64) {
        float v = s_red[tid] + s_red[tid + 64] + s_red[tid + 128] + s_red[tid + 192]
                + g_b2f[tid];
        g_a2[((size_t)b * 27 + p) * 64 + tid] = fmaxf(v, 0.f);
    }
}

// ---------------- K3a: conv3 partial sums, K split across 8 blocks per batch ---------
// grid = 16 b * 8 kc = 128 blocks. Each block: Kc=216 chunk, 256 threads
// (co = tid&127, 2-way K sub-split). Inner loop fully unrolled -> high MLP.
__global__ void conv3_partial_kernel()
{
    __shared__ float s_patch[216];
    __shared__ float s_red[256];

    int b  = blockIdx.x >> 3;
    int kc = blockIdx.x & 7;
    int tid = threadIdx.x;

    if (tid < 216) s_patch[tid] = g_a2[b * 1728 + kc * 216 + tid];
    __syncthreads();

    int co = tid & 127;
    int ks = tid >> 7;          // 2-way sub-split, 108 each
    const float* w = g_w3t + (size_t)(kc * 216 + ks * 108) * 128 + co;
    const float* p = s_patch + ks * 108;

    float a0 = 0.f, a1 = 0.f, a2 = 0.f, a3 = 0.f;
#pragma unroll
    for (int k = 0; k < 108; k += 4) {
        a0 = fmaf(p[k + 0], w[(k + 0) * 128], a0);
        a1 = fmaf(p[k + 1], w[(k + 1) * 128], a1);
        a2 = fmaf(p[k + 2], w[(k + 2) * 128], a2);
        a3 = fmaf(p[k + 3], w[(k + 3) * 128], a3);
    }
    s_red[tid] = (a0 + a1) + (a2 + a3);
    __syncthreads();

    if (tid < 128)
        g_p3[kc * 2048 + b * 128 + tid] = s_red[tid] + s_red[tid + 128];
}

// ---------------- K3b: reduce partials, BN+ReLU, then 128x256 projection ------------
__global__ void conv3_reduce_proj_kernel(const float* __restrict__ wp,
                                         const float* __restrict__ bp,
                                         float* __restrict__ out)
{
    __shared__ float s_center[128];

    int b = blockIdx.x;
    int tid = threadIdx.x;

    if (tid < 128) {
        float v = g_b3f[tid];
#pragma unroll
        for (int kc = 0; kc < 8; kc++)
            v += g_p3[kc * 2048 + b * 128 + tid];
        s_center[tid] = fmaxf(v, 0.f);
    }
    __syncthreads();

    // projection: out[b][f] = bp[f] + sum_c center[c] * wp[c*256+f]
    float o = bp[tid];
#pragma unroll
    for (int c = 0; c < 128; c++)
        o = fmaf(s_center[c], wp[c * 256 + tid], o);
    out[b * 256 + tid] = o;
}

// ---------------- launch -------------------------------------------------------------
extern "C" void kernel_launch(void* const* d_in, const int* in_sizes, int n_in,
                              void* d_out, int out_size)
{
    const float* voxel = (const float*)d_in[0];
    const float* w1 = (const float*)d_in[1];
    const float* g1 = (const float*)d_in[2];
    const float* b1 = (const float*)d_in[3];
    const float* m1 = (const float*)d_in[4];
    const float* v1 = (const float*)d_in[5];
    const float* w2 = (const float*)d_in[6];
    const float* g2 = (const float*)d_in[7];
    const float* b2 = (const float*)d_in[8];
    const float* m2 = (const float*)d_in[9];
    const float* v2 = (const float*)d_in[10];
    const float* w3 = (const float*)d_in[11];
    const float* g3 = (const float*)d_in[12];
    const float* b3 = (const float*)d_in[13];
    const float* m3 = (const float*)d_in[14];
    const float* v3 = (const float*)d_in[15];
    const float* wp = (const float*)d_in[16];
    const float* bp = (const float*)d_in[17];

    prep_kernel<<<864, 256>>>(w1, g1, b1, m1, v1,
                              w2, g2, b2, m2, v2,
                              w3, g3, b3, m3, v3);
    conv1_kernel<<<112, 256>>>(voxel);
    conv2_kernel<<<432, 256>>>();
    conv3_partial_kernel<<<128, 256>>>();
    conv3_reduce_proj_kernel<<<16, 256>>>(wp, bp, (float*)d_out);
}

// round 7
// speedup vs baseline: 3.0096x; 1.4050x over previous
#include <cuda_runtime.h>

#define BN_EPS 1e-5f

// ---------------- scratch (device globals; no allocations allowed) ----------------
__device__ float g_w2t[27 * 32 * 64];     // folded conv2 weights [(kk*32+ci)*64 + co]
__device__ float g_b2f[64];
__device__ float g_w3t[27 * 64 * 128];    // folded conv3 weights [(kk*64+ci)*128 + co]
__device__ float g_b3f[128];
__device__ float g_a1[16 * 343 * 32];     // conv1 cone activations [b][pos(7^3)][ci]
__device__ float g_a2[16 * 27 * 64];      // conv2 cone activations [b][pos(3^3)][co]
__device__ float g_p3[8 * 16 * 128];      // conv3 K-split partials [kc][b][co]
__device__ int   g_cnt;                   // conv3 arrival counter (reset by conv2)

// ---------------- K1: conv1 (blocks 0..111) + weight prep (blocks 112..255) ---------
// conv1: 16 batches * 7 z-slices; folds its own BN into w1 in smem.
// prep blocks: coalesced-read / scattered-write transpose of w2,w3 (+ b2f,b3f).
#define K1_CONV_BLOCKS 112
#define K1_PREP_BLOCKS 144
__global__ void k1_kernel(const float* __restrict__ voxel,
    const float* __restrict__ w1, const float* __restrict__ g1, const float* __restrict__ b1,
    const float* __restrict__ m1, const float* __restrict__ v1,
    const float* __restrict__ w2, const float* __restrict__ g2, const float* __restrict__ b2,
    const float* __restrict__ m2, const float* __restrict__ v2,
    const float* __restrict__ w3, const float* __restrict__ g3, const float* __restrict__ b3,
    const float* __restrict__ m3, const float* __restrict__ v3)
{
    int tid = threadIdx.x;

    if (blockIdx.x >= K1_CONV_BLOCKS) {
        // ---- prep: coalesced reads, scattered writes ----
        int gid = (blockIdx.x - K1_CONV_BLOCKS) * 256 + tid;
        const int nth = K1_PREP_BLOCKS * 256;

        // w2t[(kk*32+ci)*64+co] = w2[(co*32+ci)*27+kk] * s2[co]
        for (int j = gid; j < 55296; j += nth) {
            int co = j / 864, r = j % 864, ci = r / 27, kk = r % 27;
            float s = g2[co] * rsqrtf(v2[co] + BN_EPS);
            g_w2t[(kk * 32 + ci) * 64 + co] = w2[j] * s;
        }
        // w3t[(kk*64+ci)*128+co] = w3[(co*64+ci)*27+kk] * s3[co]
        for (int j = gid; j < 221184; j += nth) {
            int co = j / 1728, r = j % 1728, ci = r / 27, kk = r % 27;
            float s = g3[co] * rsqrtf(v3[co] + BN_EPS);
            g_w3t[(kk * 64 + ci) * 128 + co] = w3[j] * s;
        }
        if (gid < 64) {
            float s = g2[gid] * rsqrtf(v2[gid] + BN_EPS);
            g_b2f[gid] = b2[gid] - m2[gid] * s;
        } else if (gid < 192) {
            int c = gid - 64;
            float s = g3[c] * rsqrtf(v3[c] + BN_EPS);
            g_b3f[c] = b3[c] - m3[c] * s;
        }
        return;
    }

    // ---- conv1 on the 7^3 cone; output z' = 29+zi needs input z in [28+zi, 30+zi] ----
    __shared__ float s_in[3 * 9 * 9];
    __shared__ float s_w[32 * 27];
    __shared__ float s_b[32];

    int b  = blockIdx.x / 7;
    int zi = blockIdx.x % 7;

    for (int i = tid; i < 3 * 9 * 9; i += 256) {
        int lz = i / 81, r = i % 81, ly = r / 9, lx = r % 9;
        s_in[i] = voxel[(size_t)b * 262144 + (size_t)(28 + zi + lz) * 4096
                        + (28 + ly) * 64 + (28 + lx)];
    }
    for (int i = tid; i < 864; i += 256) {
        int c = i / 27;
        float s = g1[c] * rsqrtf(v1[c] + BN_EPS);
        s_w[i] = w1[i] * s;
    }
    if (tid < 32) {
        float s = g1[tid] * rsqrtf(v1[tid] + BN_EPS);
        s_b[tid] = b1[tid] - m1[tid] * s;
    }
    __syncthreads();

    if (tid < 196) {
        int pos = tid % 49;   // yi*7 + xi
        int cg  = tid / 49;   // channel group of 8
        int yi = pos / 7, xi = pos % 7;

        float x[27];
#pragma unroll
        for (int kz = 0; kz < 3; kz++)
#pragma unroll
            for (int ky = 0; ky < 3; ky++)
#pragma unroll
                for (int kx = 0; kx < 3; kx++)
                    x[kz * 9 + ky * 3 + kx] = s_in[kz * 81 + (yi + ky) * 9 + (xi + kx)];

        int p3 = zi * 49 + pos;
#pragma unroll
        for (int cc = 0; cc < 8; cc++) {
            int c = cg * 8 + cc;
            float acc = s_b[c];
#pragma unroll
            for (int k = 0; k < 27; k++)
                acc = fmaf(x[k], s_w[c * 27 + k], acc);
            g_a1[((size_t)b * 343 + p3) * 32 + c] = fmaxf(acc, 0.f);
        }
    }
}

// ---------------- K2: conv2+BN+ReLU, float4 weight loads -----------------------------
// grid = 16 b * 27 pos = 432 blocks. Thread: co4 = tid&15 (4 channels), ks = tid>>4
// (16-way K split, 54 each). 54 fully-unrolled independent LDG.128 -> MLP ~54.
__global__ void conv2_kernel()
{
    __shared__ float4 s_patch4[216];           // patch[kk*32+ci], ci as float4 lanes
    __shared__ float  s_red[16 * 64];

    int b = blockIdx.x / 27, p = blockIdx.x % 27;
    int pz = p / 9, py = (p / 3) % 3, px = p % 3;
    int tid = threadIdx.x;

    if (blockIdx.x == 0 && tid == 0) g_cnt = 0;   // reset conv3 counter each replay

    if (tid < 216) {
        int kk = tid >> 3, lane = tid & 7;
        int kz = kk / 9, ky = (kk / 3) % 3, kx = kk % 3;
        int apos = (2 * pz + kz) * 49 + (2 * py + ky) * 7 + (2 * px + kx);
        s_patch4[tid] = *(const float4*)(g_a1 + ((size_t)b * 343 + apos) * 32 + lane * 4);
    }
    __syncthreads();
    const float* s_patch = (const float*)s_patch4;

    int co4 = tid & 15;
    int ks  = tid >> 4;
    int kb  = ks * 54;
    const float4* w4 = (const float4*)g_w2t;    // [K][16 float4]
    float4 acc = {0.f, 0.f, 0.f, 0.f};
#pragma unroll
    for (int k = 0; k < 54; k++) {
        float4 w = w4[(kb + k) * 16 + co4];
        float pv = s_patch[kb + k];
        acc.x = fmaf(pv, w.x, acc.x);
        acc.y = fmaf(pv, w.y, acc.y);
        acc.z = fmaf(pv, w.z, acc.z);
        acc.w = fmaf(pv, w.w, acc.w);
    }
    *(float4*)(s_red + ks * 64 + co4 * 4) = acc;
    __syncthreads();

    if (tid < 64) {
        float v = g_b2f[tid];
#pragma unroll
        for (int s = 0; s < 16; s++) v += s_red[s * 64 + tid];
        g_a2[((size_t)b * 27 + p) * 64 + tid] = fmaxf(v, 0.f);
    }
}

// ---------------- K3: conv3 partials + co-resident tail (reduce+BN+ReLU+projection) --
// grid = 16 b * 8 kc = 128 blocks (<=148 SMs -> all co-resident, spin is safe).
// Partial: co4 = tid&31, ks = tid>>5 (8-way sub-split, 27 K each), float4 weights.
// Blocks 0..15 then spin on g_cnt==128 and finish batch = blockIdx.x.
__global__ void conv3_kernel(const float* __restrict__ wp,
                             const float* __restrict__ bp,
                             float* __restrict__ out)
{
    __shared__ float4 s_patch4[54];
    __shared__ float  s_red[8 * 128];
    __shared__ float  s_center[128];

    int b  = blockIdx.x >> 3;
    int kc = blockIdx.x & 7;
    int tid = threadIdx.x;

    if (tid < 54)
        s_patch4[tid] = *(const float4*)(g_a2 + (size_t)b * 1728 + kc * 216 + tid * 4);
    __syncthreads();
    const float* s_patch = (const float*)s_patch4;

    int co4 = tid & 31;
    int ks  = tid >> 5;
    int kb  = kc * 216 + ks * 27;
    int pb  = ks * 27;
    const float4* w4 = (const float4*)g_w3t;    // [K][32 float4]
    float4 acc = {0.f, 0.f, 0.f, 0.f};
#pragma unroll
    for (int k = 0; k < 27; k++) {
        float4 w = w4[(kb + k) * 32 + co4];
        float pv = s_patch[pb + k];
        acc.x = fmaf(pv, w.x, acc.x);
        acc.y = fmaf(pv, w.y, acc.y);
        acc.z = fmaf(pv, w.z, acc.z);
        acc.w = fmaf(pv, w.w, acc.w);
    }
    *(float4*)(s_red + ks * 128 + co4 * 4) = acc;
    __syncthreads();

    if (tid < 128) {
        float v = 0.f;
#pragma unroll
        for (int s = 0; s < 8; s++) v += s_red[s * 128 + tid];
        g_p3[kc * 2048 + b * 128 + tid] = v;
    }
    __syncthreads();
    if (tid == 0) {
        __threadfence();                 // publish this block's partials
        atomicAdd(&g_cnt, 1);
    }

    if (blockIdx.x >= 16) return;

    // ---- tail: this block finishes batch tb = blockIdx.x ----
    int tb = blockIdx.x;
    if (tid == 0) {
        while (*(volatile int*)&g_cnt < 128) { }
        __threadfence();                 // acquire all partials
    }
    __syncthreads();

    if (tid < 128) {
        float v = g_b3f[tid];
#pragma unroll
        for (int s = 0; s < 8; s++)
            v += __ldcg(&g_p3[s * 2048 + tb * 128 + tid]);   // L2 read, skip L1
        s_center[tid] = fmaxf(v, 0.f);
    }
    __syncthreads();

    // projection: out[tb][f] = bp[f] + sum_c center[c] * wp[c*256+f]
    float o = bp[tid];
#pragma unroll 8
    for (int c = 0; c < 128; c++)
        o = fmaf(s_center[c], wp[c * 256 + tid], o);
    out[tb * 256 + tid] = o;
}

// ---------------- launch -------------------------------------------------------------
extern "C" void kernel_launch(void* const* d_in, const int* in_sizes, int n_in,
                              void* d_out, int out_size)
{
    const float* voxel = (const float*)d_in[0];
    const float* w1 = (const float*)d_in[1];
    const float* g1 = (const float*)d_in[2];
    const float* b1 = (const float*)d_in[3];
    const float* m1 = (const float*)d_in[4];
    const float* v1 = (const float*)d_in[5];
    const float* w2 = (const float*)d_in[6];
    const float* g2 = (const float*)d_in[7];
    const float* b2 = (const float*)d_in[8];
    const float* m2 = (const float*)d_in[9];
    const float* v2 = (const float*)d_in[10];
    const float* w3 = (const float*)d_in[11];
    const float* g3 = (const float*)d_in[12];
    const float* b3 = (const float*)d_in[13];
    const float* m3 = (const float*)d_in[14];
    const float* v3 = (const float*)d_in[15];
    const float* wp = (const float*)d_in[16];
    const float* bp = (const float*)d_in[17];

    k1_kernel<<<K1_CONV_BLOCKS + K1_PREP_BLOCKS, 256>>>(
        voxel, w1, g1, b1, m1, v1, w2, g2, b2, m2, v2, w3, g3, b3, m3, v3);
    conv2_kernel<<<432, 256>>>();
    conv3_kernel<<<128, 256>>>(wp, bp, (float*)d_out);
}